// round 15
// baseline (speedup 1.0000x reference)
#include <cuda_runtime.h>
#include <math.h>

// Problem constants (fixed by setup_inputs)
#define BB 8
#define SS 4096
#define DD 512
#define NCHUNK 64
#define SROWS (SS / NCHUNK)   // 64 rows per k1 block
#define NGRP 16               // reduce-role d-slices of 32
#define PP 98                 // sampled partitions
#define KMAXP 6
#define MAXPART 100
#define MWPP (KMAXP * DD / 4) // 768 u32 words per partition (u8 view)

// Scratch (no allocations allowed -> __device__ globals).
__device__ __align__(16) float g_partE[NCHUNK * BB * DD];   // 1 MB
__device__ __align__(16) float g_partT[NCHUNK * BB * DD];
__device__ __align__(16) float g_sumE[BB * DD];
__device__ __align__(16) float g_sumT[BB * DD];
__device__ float g_Hfull[BB];
__device__ float g_hsingle[BB];
__device__ float g_hpk[BB * PP];
__device__ int   g_rdy = 0;     // reduce-role completion counter
__device__ int   g_cnt = 0;     // election counter (self-resetting)

// ---------------------------------------------------------------------------
// k1: streaming pass over x — EXACT R8 shape (proven 14.66us @ 4.65 TB/s).
// grid = (NCHUNK, B) = 512 blocks, 512 threads, 16 LDG.128/thread, 32 regs.
// ---------------------------------------------------------------------------
__global__ void __launch_bounds__(512) k1_stream(const float* __restrict__ x) {
    const int chunk = blockIdx.x;
    const int b     = blockIdx.y;
    const int t     = threadIdx.x;
    const int sub   = t >> 7;     // 0..3: row subset
    const int dt    = t & 127;    // float4 column

    const float4* xp = reinterpret_cast<const float4*>(
        x + ((size_t)b * SS + (size_t)chunk * SROWS) * DD)
        + (size_t)sub * (DD / 4) + dt;

    float e0 = 0.f, e1 = 0.f, e2 = 0.f, e3 = 0.f;
    float t0 = 0.f, t1 = 0.f, t2 = 0.f, t3 = 0.f;
    #pragma unroll 4
    for (int i = 0; i < SROWS / 4; i++) {
        const float4 v = xp[(size_t)i * DD];   // advance 4 rows (= DD float4)
        const float p0 = __expf(v.x), p1 = __expf(v.y),
                    p2 = __expf(v.z), p3 = __expf(v.w);
        e0 += p0; e1 += p1; e2 += p2; e3 += p3;
        t0 = fmaf(p0, v.x, t0);
        t1 = fmaf(p1, v.y, t1);
        t2 = fmaf(p2, v.z, t2);
        t3 = fmaf(p3, v.w, t3);
    }

    __shared__ __align__(16) float4 sE[4][128], sT[4][128];
    sE[sub][dt] = make_float4(e0, e1, e2, e3);
    sT[sub][dt] = make_float4(t0, t1, t2, t3);
    __syncthreads();
    if (t < 128) {
        float4 ae = sE[0][t], at = sT[0][t];
        #pragma unroll
        for (int s = 1; s < 4; s++) {
            const float4 oe = sE[s][t], ot = sT[s][t];
            ae.x += oe.x; ae.y += oe.y; ae.z += oe.z; ae.w += oe.w;
            at.x += ot.x; at.y += ot.y; at.z += ot.z; at.w += ot.w;
        }
        const int base = (chunk * BB + b) * DD;   // chunk-major
        reinterpret_cast<float4*>(g_partE + base)[t] = ae;
        reinterpret_cast<float4*>(g_partT + base)[t] = at;
    }
}

// ---------------------------------------------------------------------------
// kB: fused reduce + partitions + finalize. grid = (PP, B) = 784 blocks,
// 128 threads, ~32 regs -> ALL co-resident (100k thr << 303k) => spin-safe.
//  1) all blocks: decode this partition's mask (dtype detect per block:
//     u8 layout guarantees nonzero bytes at offset ≡1 mod 4 in the 3KB
//     region; i32/f32 0/1 guarantees all-zero; in-bounds either way).
//  2) blocks with p<16: chunk-reduce slice (g=p,b): 4 segs x 16 chunks,
//     shared combine, write g_sumE/g_sumT (same 128 blocks as old k2).
//  3) all blocks: spin g_rdy==128 (deadlock-free by co-residency), bin via
//     __ldcg; p==0 blocks emit singleton/full entropies.
//  4) threadfence election: last block runs MLP tail, resets counters.
// ---------------------------------------------------------------------------
__global__ void __launch_bounds__(128) kB(
    const void*  __restrict__ masks_raw,
    const float* __restrict__ es,  const float* __restrict__ iw,
    const float* __restrict__ W1,  const float* __restrict__ b1,
    const float* __restrict__ W2,  const float* __restrict__ b2,
    const float* __restrict__ W3,  const float* __restrict__ b3,
    float* __restrict__ out)
{
    const int p = blockIdx.x;
    const int b = blockIdx.y;
    const int t = threadIdx.x;
    const unsigned int* mw = (const unsigned int*)masks_raw;

    // ---- 1) mask decode (independent of reduce) ----
    unsigned int v = 0;
    #pragma unroll
    for (int j = t; j < MWPP; j += 128)
        v |= mw[p * MWPP + j] & 0x0000FF00u;
    const bool isU8 = (__syncthreads_or(v != 0) != 0);

    int a0 = 0, a1 = 0, a2 = 0, a3 = 0;
    if (isU8) {
        #pragma unroll
        for (int k = KMAXP - 1; k >= 0; k--) {
            const unsigned int wm = mw[(p * KMAXP + k) * (DD / 4) + t];
            if (wm & 0x000000FFu) a0 = k;
            if (wm & 0x0000FF00u) a1 = k;
            if (wm & 0x00FF0000u) a2 = k;
            if (wm & 0xFF000000u) a3 = k;
        }
    } else {
        const uint4* m4 = (const uint4*)masks_raw;
        #pragma unroll
        for (int k = KMAXP - 1; k >= 0; k--) {
            const uint4 wm = m4[(p * KMAXP + k) * (DD / 4) + t];
            if (wm.x) a0 = k;
            if (wm.y) a1 = k;
            if (wm.z) a2 = k;
            if (wm.w) a3 = k;
        }
    }

    // ---- 2) reduce role (p<16): finalize 32 d's for batch b ----
    if (p < NGRP) {
        const int seg  = t >> 5;          // 0..3, 16 chunks each
        const int lane = t & 31;
        const int d    = p * 32 + lane;
        float e = 0.f, tt = 0.f;
        #pragma unroll
        for (int i = 0; i < NCHUNK / 4; i++) {
            const int c   = seg * (NCHUNK / 4) + i;
            const int idx = (c * BB + b) * DD + d;
            e  += g_partE[idx];
            tt += g_partT[idx];
        }
        __shared__ float rE[4][32], rT[4][32];
        rE[seg][lane] = e;
        rT[seg][lane] = tt;
        __syncthreads();
        if (t < 32) {
            const float E = rE[0][t] + rE[1][t] + rE[2][t] + rE[3][t];
            const float T = rT[0][t] + rT[1][t] + rT[2][t] + rT[3][t];
            g_sumE[b * DD + p * 32 + t] = E;
            g_sumT[b * DD + p * 32 + t] = T;
        }
        __threadfence();
        __syncthreads();
        if (t == 0) atomicAdd(&g_rdy, 1);
    }

    // ---- 3) wait for all 128 reduce slices, then bin ----
    if (t == 0) {
        while (atomicAdd(&g_rdy, 0) < NGRP * BB) __nanosleep(64);
    }
    __syncthreads();

    const float4 e4 = __ldcg(reinterpret_cast<const float4*>(g_sumE + b * DD) + t);
    const float4 t4 = __ldcg(reinterpret_cast<const float4*>(g_sumT + b * DD) + t);

    // p==0 blocks also produce singleton + full-flatten entropies (R13-proven)
    if (p == 0) {
        float hs = (logf(e4.x) - t4.x / e4.x) + (logf(e4.y) - t4.y / e4.y)
                 + (logf(e4.z) - t4.z / e4.z) + (logf(e4.w) - t4.w / e4.w);
        float sEv = e4.x + e4.y + e4.z + e4.w;
        float sTv = t4.x + t4.y + t4.z + t4.w;
        #pragma unroll
        for (int o = 16; o > 0; o >>= 1) {
            hs  += __shfl_down_sync(0xffffffffu, hs,  o);
            sEv += __shfl_down_sync(0xffffffffu, sEv, o);
            sTv += __shfl_down_sync(0xffffffffu, sTv, o);
        }
        __shared__ float wH[4], wEv[4], wTv[4];
        if ((t & 31) == 0) { wH[t >> 5] = hs; wEv[t >> 5] = sEv; wTv[t >> 5] = sTv; }
        __syncthreads();
        if (t == 0) {
            const float HS = wH[0] + wH[1] + wH[2] + wH[3];
            const float E  = wEv[0] + wEv[1] + wEv[2] + wEv[3];
            const float T  = wTv[0] + wTv[1] + wTv[2] + wTv[3];
            g_hsingle[b] = HS;
            g_Hfull[b]   = logf(E) - T / E;
        }
    }

    float zk[KMAXP], tk[KMAXP];
    #pragma unroll
    for (int k = 0; k < KMAXP; k++) {
        zk[k] = (a0 == k ? e4.x : 0.f) + (a1 == k ? e4.y : 0.f)
              + (a2 == k ? e4.z : 0.f) + (a3 == k ? e4.w : 0.f);
        tk[k] = (a0 == k ? t4.x : 0.f) + (a1 == k ? t4.y : 0.f)
              + (a2 == k ? t4.z : 0.f) + (a3 == k ? t4.w : 0.f);
    }

    #pragma unroll
    for (int o = 16; o > 0; o >>= 1) {
        #pragma unroll
        for (int k = 0; k < KMAXP; k++) {
            zk[k] += __shfl_down_sync(0xffffffffu, zk[k], o);
            tk[k] += __shfl_down_sync(0xffffffffu, tk[k], o);
        }
    }
    __shared__ float sz[4][KMAXP], sst[4][KMAXP];
    const int w = t >> 5, l = t & 31;
    if (l == 0) {
        #pragma unroll
        for (int k = 0; k < KMAXP; k++) { sz[w][k] = zk[k]; sst[w][k] = tk[k]; }
    }
    __syncthreads();
    if (t == 0) {
        float hsum = 0.f;
        #pragma unroll
        for (int k = 0; k < KMAXP; k++) {
            float Z = sz[0][k] + sz[1][k] + sz[2][k] + sz[3][k];
            float T = sst[0][k] + sst[1][k] + sst[2][k] + sst[3][k];
            if (Z > 0.f) hsum += logf(Z) - T / Z;   // empty bin -> 0
        }
        g_hpk[b * PP + p] = hsum;
    }

    // ---- 4) election: is this the last block? ----
    __shared__ int s_last;
    __threadfence();
    __syncthreads();
    if (t == 0) s_last = (atomicAdd(&g_cnt, 1) == PP * BB - 1);
    __syncthreads();
    if (!s_last) return;

    // ======================= finalize tail (one block) =======================
    __shared__ float sh_min[128];
    __shared__ float sh_es[128];
    __shared__ float shF[BB], shS[BB];
    __shared__ __align__(16) float sh_w2[16 * 32];
    __shared__ float sh_w1[32], sh_b1[32], sh_b2[16], sh_w3[16], sh_b3;
    __shared__ float sh_h1[32];

    reinterpret_cast<float4*>(sh_w2)[t] = reinterpret_cast<const float4*>(W2)[t];
    if (t < 32) { sh_w1[t] = W1[t]; sh_b1[t] = b1[t]; }
    else if (t < 48) { sh_b2[t - 32] = b2[t - 32]; }
    else if (t < 64) { sh_w3[t - 48] = W3[t - 48]; }
    else if (t == 64) { sh_b3 = b3[0]; }

    if (t >= 96 && t < 96 + BB) {
        shF[t - 96] = __ldcg(&g_Hfull[t - 96]);
        shS[t - 96] = __ldcg(&g_hsingle[t - 96]);
    }

    float se = 0.f;
    #pragma unroll
    for (int i = 0; i < 4; i++) se += es[t + i * 128];
    sh_es[t] = se;
    __syncthreads();

    float wv = INFINITY;
    if (t < MAXPART) {
        float h;
        if (t == 0) {
            float s = 0.f;
            #pragma unroll
            for (int bb = 0; bb < BB; bb++) s += shF[bb];
            h = s / (float)BB;
        } else if (t == 1) {
            float s = 0.f;
            #pragma unroll
            for (int bb = 0; bb < BB; bb++) s += shS[bb];
            h = s / (float)BB;
        } else {
            float s = 0.f;
            #pragma unroll
            for (int bb = 0; bb < BB; bb++) s += __ldcg(&g_hpk[bb * PP + (t - 2)]);
            h = s / (float)BB;
        }
        const float sg = 1.f / (1.f + expf(-iw[t]));
        wv = h * sg;
    }
    sh_min[t] = wv;
    __syncthreads();

    #pragma unroll
    for (int o = 64; o > 0; o >>= 1) {
        if (t < o) {
            sh_min[t] = fminf(sh_min[t], sh_min[t + o]);
            sh_es[t] += sh_es[t + o];
        }
        __syncthreads();
    }

    if (t < 32) {
        float s = 0.f;
        #pragma unroll
        for (int bb = 0; bb < BB; bb++) s += shF[bb];
        const float h_whole = s / (float)BB;
        const float es_mean = sh_es[0] / (float)DD;

        const float raw_phi = es_mean * h_whole - sh_min[0];
        float z = fminf(fmaxf(raw_phi * 0.1f, 0.f), 1.f);

        sh_h1[t] = fmaxf(fmaf(z, sh_w1[t], sh_b1[t]), 0.f);   // h1, one per lane
        __syncwarp();

        float acc = 0.f;
        if (t < 16) {
            float a = sh_b2[t];
            #pragma unroll
            for (int j = 0; j < 32; j++) a = fmaf(sh_w2[t * 32 + j], sh_h1[j], a);
            acc = fmaxf(a, 0.f) * sh_w3[t];                    // h2[t] * W3[t]
        }
        #pragma unroll
        for (int o = 16; o > 0; o >>= 1) acc += __shfl_down_sync(0xffffffffu, acc, o);

        if (t == 0) {
            out[0] = 1.f / (1.f + expf(-(acc + sh_b3)));
            __threadfence();
            atomicExch(&g_rdy, 0);    // self-reset for the next graph replay
            atomicExch(&g_cnt, 0);
        }
    }
}

// ---------------------------------------------------------------------------
extern "C" void kernel_launch(void* const* d_in, const int* in_sizes, int n_in,
                              void* d_out, int out_size) {
    const float* x  = (const float*)d_in[0];
    const float* es = (const float*)d_in[1];
    const float* iw = (const float*)d_in[2];
    const float* W1 = (const float*)d_in[3];
    const float* b1 = (const float*)d_in[4];
    const float* W2 = (const float*)d_in[5];
    const float* b2 = (const float*)d_in[6];
    const float* W3 = (const float*)d_in[7];
    const float* b3 = (const float*)d_in[8];
    const void*  masks = (const void*)d_in[9];

    k1_stream<<<dim3(NCHUNK, BB), 512>>>(x);
    kB<<<dim3(PP, BB), 128>>>(masks, es, iw, W1, b1, W2, b2, W3, b3,
                              (float*)d_out);
}

// round 16
// speedup vs baseline: 1.0305x; 1.0305x over previous
#include <cuda_runtime.h>
#include <math.h>

// Problem constants (fixed by setup_inputs)
#define BB 8
#define SS 4096
#define DD 512
#define NCHUNK 64
#define SROWS (SS / NCHUNK)   // 64 rows per k1 block
#define NGRP 16               // reduce-role d-slices of 32
#define PP 98                 // sampled partitions
#define KMAXP 6
#define MAXPART 100
#define MWPP (KMAXP * DD / 4) // 768 u32 words per partition (u8 view)

// Scratch (no allocations allowed -> __device__ globals).
__device__ __align__(16) float g_partE[NCHUNK * BB * DD];   // 1 MB
__device__ __align__(16) float g_partT[NCHUNK * BB * DD];
__device__ __align__(16) float g_sumE[BB * DD];
__device__ __align__(16) float g_sumT[BB * DD];
__device__ float g_Hfull[BB];
__device__ float g_hsingle[BB];
__device__ float g_hpk[BB * PP];
__device__ int   g_rdy = 0;     // reduce-role completion counter
__device__ int   g_cnt = 0;     // election counter (self-resetting)

// Non-atomic L2 poll read (no RMW -> no LTS atomic-ALU serialization).
__device__ __forceinline__ int ld_cg(const int* p) {
    int v;
    asm volatile("ld.global.cg.s32 %0, [%1];" : "=r"(v) : "l"(p) : "memory");
    return v;
}

// ---------------------------------------------------------------------------
// k1: streaming pass over x — EXACT R8 shape (proven 14.66us @ 4.65 TB/s).
// grid = (NCHUNK, B) = 512 blocks, 512 threads, 16 LDG.128/thread, 32 regs.
// ---------------------------------------------------------------------------
__global__ void __launch_bounds__(512) k1_stream(const float* __restrict__ x) {
    const int chunk = blockIdx.x;
    const int b     = blockIdx.y;
    const int t     = threadIdx.x;
    const int sub   = t >> 7;     // 0..3: row subset
    const int dt    = t & 127;    // float4 column

    const float4* xp = reinterpret_cast<const float4*>(
        x + ((size_t)b * SS + (size_t)chunk * SROWS) * DD)
        + (size_t)sub * (DD / 4) + dt;

    float e0 = 0.f, e1 = 0.f, e2 = 0.f, e3 = 0.f;
    float t0 = 0.f, t1 = 0.f, t2 = 0.f, t3 = 0.f;
    #pragma unroll 4
    for (int i = 0; i < SROWS / 4; i++) {
        const float4 v = xp[(size_t)i * DD];   // advance 4 rows (= DD float4)
        const float p0 = __expf(v.x), p1 = __expf(v.y),
                    p2 = __expf(v.z), p3 = __expf(v.w);
        e0 += p0; e1 += p1; e2 += p2; e3 += p3;
        t0 = fmaf(p0, v.x, t0);
        t1 = fmaf(p1, v.y, t1);
        t2 = fmaf(p2, v.z, t2);
        t3 = fmaf(p3, v.w, t3);
    }

    __shared__ __align__(16) float4 sE[4][128], sT[4][128];
    sE[sub][dt] = make_float4(e0, e1, e2, e3);
    sT[sub][dt] = make_float4(t0, t1, t2, t3);
    __syncthreads();
    if (t < 128) {
        float4 ae = sE[0][t], at = sT[0][t];
        #pragma unroll
        for (int s = 1; s < 4; s++) {
            const float4 oe = sE[s][t], ot = sT[s][t];
            ae.x += oe.x; ae.y += oe.y; ae.z += oe.z; ae.w += oe.w;
            at.x += ot.x; at.y += ot.y; at.z += ot.z; at.w += ot.w;
        }
        const int base = (chunk * BB + b) * DD;   // chunk-major
        reinterpret_cast<float4*>(g_partE + base)[t] = ae;
        reinterpret_cast<float4*>(g_partT + base)[t] = at;
    }
}

// ---------------------------------------------------------------------------
// kB: fused reduce + partitions + finalize. grid = (PP, B) = 784 blocks,
// 128 threads, 32 regs -> ALL co-resident (100k thr << 303k) => spin-safe.
//  1) blocks with p<16: chunk-reduce FIRST (critical path), bump g_rdy.
//  2) all blocks: decode this partition's mask (dtype detect per block:
//     u8 layout guarantees nonzero bytes at offset ≡1 mod 4 in the 3KB
//     region; i32/f32 0/1 guarantees all-zero; in-bounds either way).
//  3) all blocks: NON-ATOMIC ld.cg poll until g_rdy==128, one acquire
//     atomic, fence, then bin; p==0 emits singleton/full entropies.
//  4) threadfence election: last block runs MLP tail, resets counters.
// ---------------------------------------------------------------------------
__global__ void __launch_bounds__(128) kB(
    const void*  __restrict__ masks_raw,
    const float* __restrict__ es,  const float* __restrict__ iw,
    const float* __restrict__ W1,  const float* __restrict__ b1,
    const float* __restrict__ W2,  const float* __restrict__ b2,
    const float* __restrict__ W3,  const float* __restrict__ b3,
    float* __restrict__ out)
{
    const int p = blockIdx.x;
    const int b = blockIdx.y;
    const int t = threadIdx.x;
    const unsigned int* mw = (const unsigned int*)masks_raw;

    // ---- 1) reduce role FIRST (p<16): finalize 32 d's for batch b ----
    if (p < NGRP) {
        const int seg  = t >> 5;          // 0..3, 16 chunks each
        const int lane = t & 31;
        const int d    = p * 32 + lane;
        float e = 0.f, tt = 0.f;
        #pragma unroll
        for (int i = 0; i < NCHUNK / 4; i++) {
            const int c   = seg * (NCHUNK / 4) + i;
            const int idx = (c * BB + b) * DD + d;
            e  += g_partE[idx];
            tt += g_partT[idx];
        }
        __shared__ float rE[4][32], rT[4][32];
        rE[seg][lane] = e;
        rT[seg][lane] = tt;
        __syncthreads();
        if (t < 32) {
            const float E = rE[0][t] + rE[1][t] + rE[2][t] + rE[3][t];
            const float T = rT[0][t] + rT[1][t] + rT[2][t] + rT[3][t];
            g_sumE[b * DD + p * 32 + t] = E;
            g_sumT[b * DD + p * 32 + t] = T;
        }
        __threadfence();
        __syncthreads();
        if (t == 0) atomicAdd(&g_rdy, 1);
    }

    // ---- 2) mask decode (overlaps other blocks' reduce) ----
    unsigned int v = 0;
    #pragma unroll
    for (int j = t; j < MWPP; j += 128)
        v |= mw[p * MWPP + j] & 0x0000FF00u;
    const bool isU8 = (__syncthreads_or(v != 0) != 0);

    int a0 = 0, a1 = 0, a2 = 0, a3 = 0;
    if (isU8) {
        #pragma unroll
        for (int k = KMAXP - 1; k >= 0; k--) {
            const unsigned int wm = mw[(p * KMAXP + k) * (DD / 4) + t];
            if (wm & 0x000000FFu) a0 = k;
            if (wm & 0x0000FF00u) a1 = k;
            if (wm & 0x00FF0000u) a2 = k;
            if (wm & 0xFF000000u) a3 = k;
        }
    } else {
        const uint4* m4 = (const uint4*)masks_raw;
        #pragma unroll
        for (int k = KMAXP - 1; k >= 0; k--) {
            const uint4 wm = m4[(p * KMAXP + k) * (DD / 4) + t];
            if (wm.x) a0 = k;
            if (wm.y) a1 = k;
            if (wm.z) a2 = k;
            if (wm.w) a3 = k;
        }
    }

    // ---- 3) poll (non-atomic), acquire, then bin ----
    if (t == 0) {
        while (ld_cg(&g_rdy) < NGRP * BB) __nanosleep(128);
        atomicAdd(&g_rdy, 0);             // acquire
    }
    __syncthreads();
    __threadfence();

    const float4 e4 = __ldcg(reinterpret_cast<const float4*>(g_sumE + b * DD) + t);
    const float4 t4 = __ldcg(reinterpret_cast<const float4*>(g_sumT + b * DD) + t);

    // p==0 blocks also produce singleton + full-flatten entropies
    if (p == 0) {
        float hs = (logf(e4.x) - t4.x / e4.x) + (logf(e4.y) - t4.y / e4.y)
                 + (logf(e4.z) - t4.z / e4.z) + (logf(e4.w) - t4.w / e4.w);
        float sEv = e4.x + e4.y + e4.z + e4.w;
        float sTv = t4.x + t4.y + t4.z + t4.w;
        #pragma unroll
        for (int o = 16; o > 0; o >>= 1) {
            hs  += __shfl_down_sync(0xffffffffu, hs,  o);
            sEv += __shfl_down_sync(0xffffffffu, sEv, o);
            sTv += __shfl_down_sync(0xffffffffu, sTv, o);
        }
        __shared__ float wH[4], wEv[4], wTv[4];
        if ((t & 31) == 0) { wH[t >> 5] = hs; wEv[t >> 5] = sEv; wTv[t >> 5] = sTv; }
        __syncthreads();
        if (t == 0) {
            const float HS = wH[0] + wH[1] + wH[2] + wH[3];
            const float E  = wEv[0] + wEv[1] + wEv[2] + wEv[3];
            const float T  = wTv[0] + wTv[1] + wTv[2] + wTv[3];
            g_hsingle[b] = HS;
            g_Hfull[b]   = logf(E) - T / E;
        }
    }

    float zk[KMAXP], tk[KMAXP];
    #pragma unroll
    for (int k = 0; k < KMAXP; k++) {
        zk[k] = (a0 == k ? e4.x : 0.f) + (a1 == k ? e4.y : 0.f)
              + (a2 == k ? e4.z : 0.f) + (a3 == k ? e4.w : 0.f);
        tk[k] = (a0 == k ? t4.x : 0.f) + (a1 == k ? t4.y : 0.f)
              + (a2 == k ? t4.z : 0.f) + (a3 == k ? t4.w : 0.f);
    }

    #pragma unroll
    for (int o = 16; o > 0; o >>= 1) {
        #pragma unroll
        for (int k = 0; k < KMAXP; k++) {
            zk[k] += __shfl_down_sync(0xffffffffu, zk[k], o);
            tk[k] += __shfl_down_sync(0xffffffffu, tk[k], o);
        }
    }
    __shared__ float sz[4][KMAXP], sst[4][KMAXP];
    const int w = t >> 5, l = t & 31;
    if (l == 0) {
        #pragma unroll
        for (int k = 0; k < KMAXP; k++) { sz[w][k] = zk[k]; sst[w][k] = tk[k]; }
    }
    __syncthreads();
    if (t == 0) {
        float hsum = 0.f;
        #pragma unroll
        for (int k = 0; k < KMAXP; k++) {
            float Z = sz[0][k] + sz[1][k] + sz[2][k] + sz[3][k];
            float T = sst[0][k] + sst[1][k] + sst[2][k] + sst[3][k];
            if (Z > 0.f) hsum += logf(Z) - T / Z;   // empty bin -> 0
        }
        g_hpk[b * PP + p] = hsum;
    }

    // ---- 4) election: is this the last block? ----
    __shared__ int s_last;
    __threadfence();
    __syncthreads();
    if (t == 0) s_last = (atomicAdd(&g_cnt, 1) == PP * BB - 1);
    __syncthreads();
    if (!s_last) return;

    // ======================= finalize tail (one block) =======================
    __shared__ float sh_min[128];
    __shared__ float sh_es[128];
    __shared__ float shF[BB], shS[BB];
    __shared__ __align__(16) float sh_w2[16 * 32];
    __shared__ float sh_w1[32], sh_b1[32], sh_b2[16], sh_w3[16], sh_b3;
    __shared__ float sh_h1[32];

    reinterpret_cast<float4*>(sh_w2)[t] = reinterpret_cast<const float4*>(W2)[t];
    if (t < 32) { sh_w1[t] = W1[t]; sh_b1[t] = b1[t]; }
    else if (t < 48) { sh_b2[t - 32] = b2[t - 32]; }
    else if (t < 64) { sh_w3[t - 48] = W3[t - 48]; }
    else if (t == 64) { sh_b3 = b3[0]; }

    if (t >= 96 && t < 96 + BB) {
        shF[t - 96] = __ldcg(&g_Hfull[t - 96]);
        shS[t - 96] = __ldcg(&g_hsingle[t - 96]);
    }

    float se = 0.f;
    #pragma unroll
    for (int i = 0; i < 4; i++) se += es[t + i * 128];
    sh_es[t] = se;
    __syncthreads();

    float wv = INFINITY;
    if (t < MAXPART) {
        float h;
        if (t == 0) {
            float s = 0.f;
            #pragma unroll
            for (int bb = 0; bb < BB; bb++) s += shF[bb];
            h = s / (float)BB;
        } else if (t == 1) {
            float s = 0.f;
            #pragma unroll
            for (int bb = 0; bb < BB; bb++) s += shS[bb];
            h = s / (float)BB;
        } else {
            float s = 0.f;
            #pragma unroll
            for (int bb = 0; bb < BB; bb++) s += __ldcg(&g_hpk[bb * PP + (t - 2)]);
            h = s / (float)BB;
        }
        const float sg = 1.f / (1.f + expf(-iw[t]));
        wv = h * sg;
    }
    sh_min[t] = wv;
    __syncthreads();

    #pragma unroll
    for (int o = 64; o > 0; o >>= 1) {
        if (t < o) {
            sh_min[t] = fminf(sh_min[t], sh_min[t + o]);
            sh_es[t] += sh_es[t + o];
        }
        __syncthreads();
    }

    if (t < 32) {
        float s = 0.f;
        #pragma unroll
        for (int bb = 0; bb < BB; bb++) s += shF[bb];
        const float h_whole = s / (float)BB;
        const float es_mean = sh_es[0] / (float)DD;

        const float raw_phi = es_mean * h_whole - sh_min[0];
        float z = fminf(fmaxf(raw_phi * 0.1f, 0.f), 1.f);

        sh_h1[t] = fmaxf(fmaf(z, sh_w1[t], sh_b1[t]), 0.f);   // h1, one per lane
        __syncwarp();

        float acc = 0.f;
        if (t < 16) {
            float a = sh_b2[t];
            #pragma unroll
            for (int j = 0; j < 32; j++) a = fmaf(sh_w2[t * 32 + j], sh_h1[j], a);
            acc = fmaxf(a, 0.f) * sh_w3[t];                    // h2[t] * W3[t]
        }
        #pragma unroll
        for (int o = 16; o > 0; o >>= 1) acc += __shfl_down_sync(0xffffffffu, acc, o);

        if (t == 0) {
            out[0] = 1.f / (1.f + expf(-(acc + sh_b3)));
            __threadfence();
            atomicExch(&g_rdy, 0);    // self-reset for the next graph replay
            atomicExch(&g_cnt, 0);
        }
    }
}

// ---------------------------------------------------------------------------
extern "C" void kernel_launch(void* const* d_in, const int* in_sizes, int n_in,
                              void* d_out, int out_size) {
    const float* x  = (const float*)d_in[0];
    const float* es = (const float*)d_in[1];
    const float* iw = (const float*)d_in[2];
    const float* W1 = (const float*)d_in[3];
    const float* b1 = (const float*)d_in[4];
    const float* W2 = (const float*)d_in[5];
    const float* b2 = (const float*)d_in[6];
    const float* W3 = (const float*)d_in[7];
    const float* b3 = (const float*)d_in[8];
    const void*  masks = (const void*)d_in[9];

    k1_stream<<<dim3(NCHUNK, BB), 512>>>(x);
    kB<<<dim3(PP, BB), 128>>>(masks, es, iw, W1, b1, W2, b2, W3, b3,
                              (float*)d_out);
}